// round 1
// baseline (speedup 1.0000x reference)
#include <cuda_runtime.h>

// Problem constants (fixed by the dataset)
#define B   4
#define P   12000
#define NF  64
#define XS  512
#define YS  512
#define GRID_CELLS (XS * YS)            // 262144
#define OUT_ELEMS  (B * NF * GRID_CELLS) // 67,108,864 floats = 256 MB

// ---------------------------------------------------------------------------
// Kernel 1: zero the entire 256 MB output with 128-bit stores.
// Exact mapping: one float4 store per thread, no guard needed (OUT_ELEMS/4
// divides evenly by block*grid below).
// ---------------------------------------------------------------------------
__global__ void zero_out_kernel(float4* __restrict__ out) {
    unsigned int i = blockIdx.x * blockDim.x + threadIdx.x;
    out[i] = make_float4(0.f, 0.f, 0.f, 0.f);
}

// ---------------------------------------------------------------------------
// Kernel 2: scatter-add. One thread per (b, p, f) with f fastest so that
//   - pillar value loads are fully coalesced (t == linear pillar index)
//   - coord / contains loads are warp-uniform broadcasts
// Output element: out[b, f, y, x] with flat grid index idx = y*XS + x.
// atomicAdd with unused result -> REDG (no return trip).
// ---------------------------------------------------------------------------
__global__ void scatter_add_kernel(const float* __restrict__ pillars,
                                   const int*   __restrict__ coord,
                                   const int*   __restrict__ contains,
                                   float*       __restrict__ out) {
    unsigned int t  = blockIdx.x * blockDim.x + threadIdx.x; // [0, B*P*NF)
    unsigned int f  = t & (NF - 1);
    unsigned int bp = t >> 6;            // [0, B*P)

    if (contains[bp] != 1) return;

    float v = pillars[t];
    int y = coord[bp * 3 + 1];
    int x = coord[bp * 3 + 2];
    unsigned int idx = (unsigned int)(y * XS + x);

    unsigned int b = bp / P;
    unsigned int plane = b * NF + f;     // [0, 256)
    atomicAdd(&out[(plane << 18) + idx], v);
}

extern "C" void kernel_launch(void* const* d_in, const int* in_sizes, int n_in,
                              void* d_out, int out_size) {
    const float* pillars  = (const float*)d_in[0];  // [B, P, NF] fp32
    const int*   coord    = (const int*)  d_in[1];  // [B, P, 3]  int32
    const int*   contains = (const int*)  d_in[2];  // [B, P]     int32
    float*       out      = (float*)d_out;          // [B, NF, XS, YS] fp32

    // 1) Zero 256 MB output: 16,777,216 float4 stores.
    {
        const int threads = 256;
        const int blocks  = (OUT_ELEMS / 4) / threads; // 65536, exact
        zero_out_kernel<<<blocks, threads>>>((float4*)out);
    }

    // 2) Scatter-add 3,072,000 values.
    {
        const int threads = 256;
        const int blocks  = (B * P * NF) / threads;    // 12000, exact
        scatter_add_kernel<<<blocks, threads>>>(pillars, coord, contains, out);
    }
}